// round 2
// baseline (speedup 1.0000x reference)
#include <cuda_runtime.h>

// SimpleSSM: h_t = A*h_{t-1} + B*x_t ; y_t = C*h_t + D*x_t ; out = LayerNorm_dm(y)
// x: [8, 4096, 1024] f32. Diagonal recurrence -> chunked parallel scan + fused LN.
//
// R2 plan: phase1 with 4x blocks (L=16), phase2 channel-per-thread into a
// separate h_in array, phase3 with 2 timesteps per reduction round (half the
// barriers), 1024 blocks, streaming ld/st.

#define BSZ       8
#define SEQ_T     4096
#define DM        1024
#define DM4       (DM / 4)

#define N1        256                 // phase1 chunks per batch
#define L1        (SEQ_T / N1)        // 16 timesteps per phase1 chunk
#define N3        128                 // phase3 chunks per batch
#define L3        (SEQ_T / N3)        // 32 timesteps per phase3 chunk

#define LN_EPS    1e-5f
#define NTHREADS  256

// Phase1 output: local chunk sums s_c, [BSZ][N1][DM]  (8 MB)
__device__ float g_carry[BSZ * N1 * DM];
// Phase2 output: h at the start of each 16-chunk, [BSZ][N1][DM]  (8 MB)
__device__ float g_hin[BSZ * N1 * DM];

// ---------------------------------------------------------------------------
// Phase 1: chunk-local scan with the reference's forward recurrence.
// ---------------------------------------------------------------------------
__global__ __launch_bounds__(NTHREADS)
void ssm_phase1(const float* __restrict__ x,
                const float4* __restrict__ A4,
                const float4* __restrict__ B4) {
    const int blk = blockIdx.x;              // b * N1 + c
    const int b   = blk >> 8;
    const int c   = blk & (N1 - 1);
    const int tid = threadIdx.x;

    const float4 a  = A4[tid];
    const float4 bb = B4[tid];

    const float4* xp = reinterpret_cast<const float4*>(x)
                     + (size_t)(b * SEQ_T + c * L1) * DM4 + tid;

    float4 s = make_float4(0.f, 0.f, 0.f, 0.f);
    #pragma unroll
    for (int t = 0; t < L1; t++) {
        float4 xv = xp[(size_t)t * DM4];
        s.x = fmaf(a.x, s.x, bb.x * xv.x);
        s.y = fmaf(a.y, s.y, bb.y * xv.y);
        s.z = fmaf(a.z, s.z, bb.z * xv.z);
        s.w = fmaf(a.w, s.w, bb.w * xv.w);
    }
    reinterpret_cast<float4*>(g_carry)[(size_t)(b * N1 + c) * DM4 + tid] = s;
}

// ---------------------------------------------------------------------------
// Phase 2: per-(b, channel) scan over the N1 chunk sums (hits L2):
//   H_{-1}=0 ; g_hin[c] = H_{c-1} ; H_c = A^L1 * H_{c-1} + s_c
// 8192 independent scalar chains, one per thread.
// ---------------------------------------------------------------------------
__global__ __launch_bounds__(NTHREADS)
void ssm_phase2(const float* __restrict__ A) {
    const int gid = blockIdx.x * NTHREADS + threadIdx.x;   // [0, 8192)
    const int b   = gid >> 10;
    const int ch  = gid & (DM - 1);

    float aL = A[ch];
    #pragma unroll
    for (int i = 0; i < 4; i++) aL *= aL;    // A^16

    const float* __restrict__ src = g_carry + (size_t)b * N1 * DM + ch;
    float*       __restrict__ dst = g_hin   + (size_t)b * N1 * DM + ch;

    float h = 0.f;
    #pragma unroll 16
    for (int c = 0; c < N1; c++) {
        float s = src[(size_t)c * DM];
        dst[(size_t)c * DM] = h;
        h = fmaf(aL, h, s);
    }
}

// ---------------------------------------------------------------------------
// Phase 3: one block per (b, 32-step chunk). Each thread owns 4 channels.
// Two timesteps per reduction round -> 2 barriers per 2 timesteps.
// ---------------------------------------------------------------------------
__global__ __launch_bounds__(NTHREADS)
void ssm_phase3(const float* __restrict__ x,
                const float4* __restrict__ A4,
                const float4* __restrict__ B4,
                const float4* __restrict__ C4,
                const float4* __restrict__ D4,
                const float4* __restrict__ G4,
                const float4* __restrict__ E4,
                float* __restrict__ out) {
    __shared__ float red1[2][8];
    __shared__ float red2[2][8];
    __shared__ float stats[2][2];            // [timestep in round][mu, rstd]

    const int blk  = blockIdx.x;             // b * N3 + c
    const int b    = blk >> 7;
    const int c    = blk & (N3 - 1);
    const int tid  = threadIdx.x;
    const int lane = tid & 31;
    const int wid  = tid >> 5;

    const float4 a  = A4[tid];
    const float4 bb = B4[tid];
    const float4 cc = C4[tid];
    const float4 dd = D4[tid];
    const float4 g  = G4[tid];
    const float4 be = E4[tid];

    // h at the start of this 32-step chunk = g_hin at 16-chunk index 2c.
    float4 h = reinterpret_cast<const float4*>(g_hin)
                   [(size_t)(b * N1 + 2 * c) * DM4 + tid];

    const size_t row0 = (size_t)(b * SEQ_T + c * L3) * DM4 + tid;
    const float4* xp = reinterpret_cast<const float4*>(x) + row0;
    float4*       op = reinterpret_cast<float4*>(out)     + row0;

    float4 x0 = __ldcs(xp);
    float4 x1 = __ldcs(xp + DM4);

    #pragma unroll 4
    for (int r = 0; r < L3 / 2; r++) {
        // Prefetch next round's rows (clamped; tail re-reads hit L2).
        const int t2 = (2 * r + 2 < L3) ? (2 * r + 2) : (L3 - 1);
        const int t3 = (2 * r + 3 < L3) ? (2 * r + 3) : (L3 - 1);
        float4 p0 = __ldcs(xp + (size_t)t2 * DM4);
        float4 p1 = __ldcs(xp + (size_t)t3 * DM4);

        // Recurrence for two timesteps.
        h.x = fmaf(a.x, h.x, bb.x * x0.x);
        h.y = fmaf(a.y, h.y, bb.y * x0.y);
        h.z = fmaf(a.z, h.z, bb.z * x0.z);
        h.w = fmaf(a.w, h.w, bb.w * x0.w);
        float4 y0;
        y0.x = fmaf(cc.x, h.x, dd.x * x0.x);
        y0.y = fmaf(cc.y, h.y, dd.y * x0.y);
        y0.z = fmaf(cc.z, h.z, dd.z * x0.z);
        y0.w = fmaf(cc.w, h.w, dd.w * x0.w);

        h.x = fmaf(a.x, h.x, bb.x * x1.x);
        h.y = fmaf(a.y, h.y, bb.y * x1.y);
        h.z = fmaf(a.z, h.z, bb.z * x1.z);
        h.w = fmaf(a.w, h.w, bb.w * x1.w);
        float4 y1;
        y1.x = fmaf(cc.x, h.x, dd.x * x1.x);
        y1.y = fmaf(cc.y, h.y, dd.y * x1.y);
        y1.z = fmaf(cc.z, h.z, dd.z * x1.z);
        y1.w = fmaf(cc.w, h.w, dd.w * x1.w);

        // Partial sums for both timesteps.
        float s10 = y0.x + y0.y + y0.z + y0.w;
        float s20 = fmaf(y0.x, y0.x, fmaf(y0.y, y0.y, fmaf(y0.z, y0.z, y0.w * y0.w)));
        float s11 = y1.x + y1.y + y1.z + y1.w;
        float s21 = fmaf(y1.x, y1.x, fmaf(y1.y, y1.y, fmaf(y1.z, y1.z, y1.w * y1.w)));

        #pragma unroll
        for (int off = 16; off > 0; off >>= 1) {
            s10 += __shfl_xor_sync(0xFFFFFFFFu, s10, off);
            s20 += __shfl_xor_sync(0xFFFFFFFFu, s20, off);
            s11 += __shfl_xor_sync(0xFFFFFFFFu, s11, off);
            s21 += __shfl_xor_sync(0xFFFFFFFFu, s21, off);
        }
        if (lane == 0) {
            red1[0][wid] = s10; red2[0][wid] = s20;
            red1[1][wid] = s11; red2[1][wid] = s21;
        }
        __syncthreads();

        if (tid < 16) {
            const int w  = tid & 7;          // warp index
            const int rr = tid >> 3;         // timestep within round
            float v1 = red1[rr][w];
            float v2 = red2[rr][w];
            #pragma unroll
            for (int off = 4; off > 0; off >>= 1) {
                v1 += __shfl_down_sync(0x0000FFFFu, v1, off);
                v2 += __shfl_down_sync(0x0000FFFFu, v2, off);
            }
            if (w == 0) {
                float mu  = v1 * (1.f / DM);
                float var = fmaf(v2, 1.f / DM, -mu * mu);
                if (var < 0.f) var = 0.f;
                stats[rr][0] = mu;
                stats[rr][1] = rsqrtf(var + LN_EPS);
            }
        }
        __syncthreads();

        const float mu0 = stats[0][0], rs0 = stats[0][1];
        const float mu1 = stats[1][0], rs1 = stats[1][1];

        float4 o;
        o.x = fmaf((y0.x - mu0) * rs0, g.x, be.x);
        o.y = fmaf((y0.y - mu0) * rs0, g.y, be.y);
        o.z = fmaf((y0.z - mu0) * rs0, g.z, be.z);
        o.w = fmaf((y0.w - mu0) * rs0, g.w, be.w);
        __stcs(op + (size_t)(2 * r) * DM4, o);

        o.x = fmaf((y1.x - mu1) * rs1, g.x, be.x);
        o.y = fmaf((y1.y - mu1) * rs1, g.y, be.y);
        o.z = fmaf((y1.z - mu1) * rs1, g.z, be.z);
        o.w = fmaf((y1.w - mu1) * rs1, g.w, be.w);
        __stcs(op + (size_t)(2 * r + 1) * DM4, o);

        x0 = p0;
        x1 = p1;
    }
}

// ---------------------------------------------------------------------------
extern "C" void kernel_launch(void* const* d_in, const int* in_sizes, int n_in,
                              void* d_out, int out_size) {
    const float*  x  = (const float*)d_in[0];
    const float*  A  = (const float*)d_in[1];
    const float4* A4 = (const float4*)d_in[1];
    const float4* B4 = (const float4*)d_in[2];
    const float4* C4 = (const float4*)d_in[3];
    const float4* D4 = (const float4*)d_in[4];
    const float4* G4 = (const float4*)d_in[5];
    const float4* E4 = (const float4*)d_in[6];
    float* out = (float*)d_out;

    ssm_phase1<<<BSZ * N1, NTHREADS>>>(x, A4, B4);
    ssm_phase2<<<(BSZ * DM) / NTHREADS, NTHREADS>>>(A);
    ssm_phase3<<<BSZ * N3, NTHREADS>>>(x, A4, B4, C4, D4, G4, E4, out);
}

// round 3
// speedup vs baseline: 1.0709x; 1.0709x over previous
#include <cuda_runtime.h>

// SimpleSSM: h_t = A*h_{t-1} + B*x_t ; y_t = C*h_t + D*x_t ; out = LayerNorm_dm(y)
// x: [8, 4096, 1024] f32. Chunked parallel scan + fused LN.
//
// R3: phase3 redesigned — 4 timesteps per barrier round, register double-buffer
// prefetch (full round ahead), parallel 2nd-stage stats across warps 0-3.

#define BSZ       8
#define SEQ_T     4096
#define DM        1024
#define DM4       (DM / 4)

#define N1        256                 // phase1 chunks per batch
#define L1        (SEQ_T / N1)        // 16
#define N3        128                 // phase3 chunks per batch
#define L3        (SEQ_T / N3)        // 32
#define RSTEPS    4                   // timesteps per reduction round
#define NROUNDS   (L3 / RSTEPS)       // 8

#define LN_EPS    1e-5f
#define NTHREADS  256

__device__ float g_carry[BSZ * N1 * DM];   // phase1 chunk-local sums (8 MB)
__device__ float g_hin[BSZ * N1 * DM];     // state at each 16-chunk start (8 MB)

// ---------------------------------------------------------------------------
// Phase 1: chunk-local scan with the reference's forward recurrence.
// ---------------------------------------------------------------------------
__global__ __launch_bounds__(NTHREADS)
void ssm_phase1(const float* __restrict__ x,
                const float4* __restrict__ A4,
                const float4* __restrict__ B4) {
    const int blk = blockIdx.x;
    const int b   = blk >> 8;
    const int c   = blk & (N1 - 1);
    const int tid = threadIdx.x;

    const float4 a  = A4[tid];
    const float4 bb = B4[tid];

    const float4* xp = reinterpret_cast<const float4*>(x)
                     + (size_t)(b * SEQ_T + c * L1) * DM4 + tid;

    float4 s = make_float4(0.f, 0.f, 0.f, 0.f);
    #pragma unroll
    for (int t = 0; t < L1; t++) {
        float4 xv = xp[(size_t)t * DM4];
        s.x = fmaf(a.x, s.x, bb.x * xv.x);
        s.y = fmaf(a.y, s.y, bb.y * xv.y);
        s.z = fmaf(a.z, s.z, bb.z * xv.z);
        s.w = fmaf(a.w, s.w, bb.w * xv.w);
    }
    reinterpret_cast<float4*>(g_carry)[(size_t)(b * N1 + c) * DM4 + tid] = s;
}

// ---------------------------------------------------------------------------
// Phase 2: per-(b, channel) scan over the N1 chunk sums:
//   H_{-1}=0 ; g_hin[c] = H_{c-1} ; H_c = A^L1 * H_{c-1} + s_c
// ---------------------------------------------------------------------------
__global__ __launch_bounds__(NTHREADS)
void ssm_phase2(const float* __restrict__ A) {
    const int gid = blockIdx.x * NTHREADS + threadIdx.x;   // [0, 8192)
    const int b   = gid >> 10;
    const int ch  = gid & (DM - 1);

    float aL = A[ch];
    #pragma unroll
    for (int i = 0; i < 4; i++) aL *= aL;    // A^16

    const float* __restrict__ src = g_carry + (size_t)b * N1 * DM + ch;
    float*       __restrict__ dst = g_hin   + (size_t)b * N1 * DM + ch;

    float h = 0.f;
    #pragma unroll 16
    for (int c = 0; c < N1; c++) {
        float s = src[(size_t)c * DM];
        dst[(size_t)c * DM] = h;
        h = fmaf(aL, h, s);
    }
}

// ---------------------------------------------------------------------------
// Phase 3: one block per (b, 32-step chunk). Thread owns one float4 column.
// 4 timesteps per barrier round; next round's rows prefetched into registers.
// ---------------------------------------------------------------------------
__global__ __launch_bounds__(NTHREADS)
void ssm_phase3(const float* __restrict__ x,
                const float4* __restrict__ A4,
                const float4* __restrict__ B4,
                const float4* __restrict__ C4,
                const float4* __restrict__ D4,
                const float4* __restrict__ G4,
                const float4* __restrict__ E4,
                float* __restrict__ out) {
    __shared__ float  red1[RSTEPS][8];
    __shared__ float  red2[RSTEPS][8];
    __shared__ float2 stats[RSTEPS];         // (mu, rstd)

    const int blk  = blockIdx.x;             // b * N3 + c
    const int b    = blk >> 7;
    const int c    = blk & (N3 - 1);
    const int tid  = threadIdx.x;
    const int lane = tid & 31;
    const int wid  = tid >> 5;

    const float4 a  = A4[tid];
    const float4 bb = B4[tid];
    const float4 cc = C4[tid];
    const float4 dd = D4[tid];
    const float4 g  = G4[tid];
    const float4 be = E4[tid];

    float4 h = reinterpret_cast<const float4*>(g_hin)
                   [(size_t)(b * N1 + 2 * c) * DM4 + tid];

    const size_t row0 = (size_t)(b * SEQ_T + c * L3) * DM4 + tid;
    const float4* xp = reinterpret_cast<const float4*>(x) + row0;
    float4*       op = reinterpret_cast<float4*>(out)     + row0;

    float4 cur0 = xp[0 * DM4];
    float4 cur1 = xp[1 * DM4];
    float4 cur2 = xp[2 * DM4];
    float4 cur3 = xp[3 * DM4];

    #pragma unroll 1
    for (int r = 0; r < NROUNDS; r++) {
        // Prefetch the whole next round (issued before any dependent work).
        float4 nxt0, nxt1, nxt2, nxt3;
        if (r + 1 < NROUNDS) {
            const size_t base = (size_t)((r + 1) * RSTEPS) * DM4;
            nxt0 = xp[base + 0 * DM4];
            nxt1 = xp[base + 1 * DM4];
            nxt2 = xp[base + 2 * DM4];
            nxt3 = xp[base + 3 * DM4];
        }

        float4 y[RSTEPS];
        float  s1[RSTEPS], s2[RSTEPS];

        #pragma unroll
        for (int i = 0; i < RSTEPS; i++) {
            const float4 xv = (i == 0) ? cur0 : (i == 1) ? cur1 : (i == 2) ? cur2 : cur3;
            h.x = fmaf(a.x, h.x, bb.x * xv.x);
            h.y = fmaf(a.y, h.y, bb.y * xv.y);
            h.z = fmaf(a.z, h.z, bb.z * xv.z);
            h.w = fmaf(a.w, h.w, bb.w * xv.w);
            y[i].x = fmaf(cc.x, h.x, dd.x * xv.x);
            y[i].y = fmaf(cc.y, h.y, dd.y * xv.y);
            y[i].z = fmaf(cc.z, h.z, dd.z * xv.z);
            y[i].w = fmaf(cc.w, h.w, dd.w * xv.w);
            s1[i] = y[i].x + y[i].y + y[i].z + y[i].w;
            s2[i] = fmaf(y[i].x, y[i].x,
                    fmaf(y[i].y, y[i].y,
                    fmaf(y[i].z, y[i].z, y[i].w * y[i].w)));
        }

        // Warp-level reduction for all 4 timesteps (independent, pipelined).
        #pragma unroll
        for (int off = 16; off > 0; off >>= 1) {
            #pragma unroll
            for (int i = 0; i < RSTEPS; i++) {
                s1[i] += __shfl_xor_sync(0xFFFFFFFFu, s1[i], off);
                s2[i] += __shfl_xor_sync(0xFFFFFFFFu, s2[i], off);
            }
        }
        if (lane == 0) {
            #pragma unroll
            for (int i = 0; i < RSTEPS; i++) {
                red1[i][wid] = s1[i];
                red2[i][wid] = s2[i];
            }
        }
        __syncthreads();

        // Warps 0..3 each finalize one timestep's stats in parallel.
        if (wid < RSTEPS && lane < 8) {
            float v1 = red1[wid][lane];
            float v2 = red2[wid][lane];
            #pragma unroll
            for (int off = 4; off > 0; off >>= 1) {
                v1 += __shfl_down_sync(0x000000FFu, v1, off, 8);
                v2 += __shfl_down_sync(0x000000FFu, v2, off, 8);
            }
            if (lane == 0) {
                float mu  = v1 * (1.f / DM);
                float var = fmaf(v2, 1.f / DM, -mu * mu);
                if (var < 0.f) var = 0.f;
                stats[wid] = make_float2(mu, rsqrtf(var + LN_EPS));
            }
        }
        __syncthreads();

        #pragma unroll
        for (int i = 0; i < RSTEPS; i++) {
            const float2 st = stats[i];
            float4 o;
            o.x = fmaf((y[i].x - st.x) * st.y, g.x, be.x);
            o.y = fmaf((y[i].y - st.x) * st.y, g.y, be.y);
            o.z = fmaf((y[i].z - st.x) * st.y, g.z, be.z);
            o.w = fmaf((y[i].w - st.x) * st.y, g.w, be.w);
            op[(size_t)(r * RSTEPS + i) * DM4] = o;
        }

        cur0 = nxt0; cur1 = nxt1; cur2 = nxt2; cur3 = nxt3;
    }
}

// ---------------------------------------------------------------------------
extern "C" void kernel_launch(void* const* d_in, const int* in_sizes, int n_in,
                              void* d_out, int out_size) {
    const float*  x  = (const float*)d_in[0];
    const float*  A  = (const float*)d_in[1];
    const float4* A4 = (const float4*)d_in[1];
    const float4* B4 = (const float4*)d_in[2];
    const float4* C4 = (const float4*)d_in[3];
    const float4* D4 = (const float4*)d_in[4];
    const float4* G4 = (const float4*)d_in[5];
    const float4* E4 = (const float4*)d_in[6];
    float* out = (float*)d_out;

    ssm_phase1<<<BSZ * N1, NTHREADS>>>(x, A4, B4);
    ssm_phase2<<<(BSZ * DM) / NTHREADS, NTHREADS>>>(A);
    ssm_phase3<<<BSZ * N3, NTHREADS>>>(x, A4, B4, C4, D4, G4, E4, out);
}